// round 1
// baseline (speedup 1.0000x reference)
#include <cuda_runtime.h>
#include <math.h>

#define BATCH 4
#define SEQ   2048
#define DMODEL 1024
#define NHEAD 16
#define HDIM  64
#define NTOK  (BATCH*SEQ)   // 8192

// Scratch (device globals; allocation is forbidden)
__device__ float g_Q[(size_t)NTOK * DMODEL];
__device__ float g_K[(size_t)NTOK * DMODEL];
__device__ float g_V[(size_t)NTOK * DMODEL];
__device__ float g_ctx[(size_t)NTOK * DMODEL];

// ---------------------------------------------------------------------------
// QKV projection GEMM:  out[b,h,s,hd] = sum_k X[m,k]*W[n,k] + bias[n]
//   m = b*SEQ+s (token), n = h*HDIM+hd
// Tile 64x64, K-step 32, 256 threads, 4x4 per thread.
// ---------------------------------------------------------------------------
__global__ void qkv_gemm_kernel(const float* __restrict__ X,
                                const float* __restrict__ W,
                                const float* __restrict__ bias,
                                float* __restrict__ out)
{
    __shared__ float As[64][33];
    __shared__ float Bs[64][33];

    const int bm = blockIdx.y * 64;   // token tile
    const int bn = blockIdx.x * 64;   // output-dim tile (exactly one head)
    const int tid = threadIdx.x;
    const int tx = tid & 15;
    const int ty = tid >> 4;

    float acc[4][4] = {};

    for (int k0 = 0; k0 < DMODEL; k0 += 32) {
        // load A (64x32) and B (64x32) as float4, 2 per thread each
        #pragma unroll
        for (int r = 0; r < 2; ++r) {
            int f   = tid + r * 256;      // 0..511
            int row = f >> 3;             // 0..63
            int c4  = (f & 7) << 2;       // 0,4,...,28
            float4 a = *(const float4*)(X + (size_t)(bm + row) * DMODEL + k0 + c4);
            As[row][c4 + 0] = a.x; As[row][c4 + 1] = a.y;
            As[row][c4 + 2] = a.z; As[row][c4 + 3] = a.w;
            float4 b = *(const float4*)(W + (size_t)(bn + row) * DMODEL + k0 + c4);
            Bs[row][c4 + 0] = b.x; Bs[row][c4 + 1] = b.y;
            Bs[row][c4 + 2] = b.z; Bs[row][c4 + 3] = b.w;
        }
        __syncthreads();

        #pragma unroll 8
        for (int kk = 0; kk < 32; ++kk) {
            float a[4], b[4];
            #pragma unroll
            for (int i = 0; i < 4; ++i) a[i] = As[ty * 4 + i][kk];
            #pragma unroll
            for (int j = 0; j < 4; ++j) b[j] = Bs[tx * 4 + j][kk];
            #pragma unroll
            for (int i = 0; i < 4; ++i)
                #pragma unroll
                for (int j = 0; j < 4; ++j)
                    acc[i][j] = fmaf(a[i], b[j], acc[i][j]);
        }
        __syncthreads();
    }

    // epilogue: add bias, scatter to [b,h,s,hd]
    #pragma unroll
    for (int i = 0; i < 4; ++i) {
        int m = bm + ty * 4 + i;
        int bb = m / SEQ;
        int ss = m % SEQ;
        #pragma unroll
        for (int j = 0; j < 4; ++j) {
            int n = bn + tx * 4 + j;
            int h = n / HDIM;
            int hd = n % HDIM;
            out[(((size_t)bb * NHEAD + h) * SEQ + ss) * HDIM + hd] = acc[i][j] + bias[n];
        }
    }
}

// ---------------------------------------------------------------------------
// Flash attention (fp32). One block = (b,h, 64-query tile).
// 256 threads as 16x16: thread owns scores[4q][2k] and O[4q][4hd].
// ---------------------------------------------------------------------------
__global__ void attn_kernel(const float* __restrict__ Q,
                            const float* __restrict__ K,
                            const float* __restrict__ V,
                            float* __restrict__ ctx)
{
    const int qt = blockIdx.x;         // query tile index (0..31)
    const int bh = blockIdx.y;         // b*NHEAD + h
    const int b  = bh / NHEAD;
    const int h  = bh % NHEAD;

    __shared__ float Qs[64][65];
    __shared__ float Ks[32][65];
    __shared__ float Vs[32][65];
    __shared__ float Ps[64][33];

    const int tid = threadIdx.x;
    const int tx  = tid & 15;
    const int ty  = tid >> 4;

    // load Q tile (64x64), 4 float4 per thread
    const float* Qp = Q + ((size_t)bh * SEQ + qt * 64) * HDIM;
    #pragma unroll
    for (int r = 0; r < 4; ++r) {
        int f = tid + r * 256;          // 0..1023
        int row = f >> 4;
        int c4  = (f & 15) << 2;
        float4 v = *(const float4*)(Qp + row * HDIM + c4);
        Qs[row][c4 + 0] = v.x; Qs[row][c4 + 1] = v.y;
        Qs[row][c4 + 2] = v.z; Qs[row][c4 + 3] = v.w;
    }

    float m_i[4], l_i[4], o[4][4];
    #pragma unroll
    for (int i = 0; i < 4; ++i) {
        m_i[i] = -INFINITY; l_i[i] = 0.f;
        #pragma unroll
        for (int j = 0; j < 4; ++j) o[i][j] = 0.f;
    }

    const float scale = 0.125f;   // 1/sqrt(64)
    const float* Kbase = K + (size_t)bh * SEQ * HDIM;
    const float* Vbase = V + (size_t)bh * SEQ * HDIM;

    __syncthreads();

    for (int kt = 0; kt < SEQ / 32; ++kt) {
        // load K,V tiles (32x64 each), 2 float4 per thread per tile
        const float* Kp = Kbase + (size_t)kt * 32 * HDIM;
        const float* Vp = Vbase + (size_t)kt * 32 * HDIM;
        #pragma unroll
        for (int r = 0; r < 2; ++r) {
            int f = tid + r * 256;       // 0..511
            int row = f >> 4;            // 0..31
            int c4  = (f & 15) << 2;
            float4 kv = *(const float4*)(Kp + row * HDIM + c4);
            Ks[row][c4 + 0] = kv.x; Ks[row][c4 + 1] = kv.y;
            Ks[row][c4 + 2] = kv.z; Ks[row][c4 + 3] = kv.w;
            float4 vv = *(const float4*)(Vp + row * HDIM + c4);
            Vs[row][c4 + 0] = vv.x; Vs[row][c4 + 1] = vv.y;
            Vs[row][c4 + 2] = vv.z; Vs[row][c4 + 3] = vv.w;
        }
        __syncthreads();

        // scores: s[4q][2k] = Q . K
        float s[4][2] = {};
        #pragma unroll 16
        for (int hd = 0; hd < 64; ++hd) {
            float q0 = Qs[ty * 4 + 0][hd];
            float q1 = Qs[ty * 4 + 1][hd];
            float q2 = Qs[ty * 4 + 2][hd];
            float q3 = Qs[ty * 4 + 3][hd];
            float k0 = Ks[tx * 2 + 0][hd];
            float k1 = Ks[tx * 2 + 1][hd];
            s[0][0] = fmaf(q0, k0, s[0][0]); s[0][1] = fmaf(q0, k1, s[0][1]);
            s[1][0] = fmaf(q1, k0, s[1][0]); s[1][1] = fmaf(q1, k1, s[1][1]);
            s[2][0] = fmaf(q2, k0, s[2][0]); s[2][1] = fmaf(q2, k1, s[2][1]);
            s[3][0] = fmaf(q3, k0, s[3][0]); s[3][1] = fmaf(q3, k1, s[3][1]);
        }

        // online softmax per query row (16-lane shuffle reductions across tx)
        #pragma unroll
        for (int i = 0; i < 4; ++i) {
            float sm0 = s[i][0] * scale;
            float sm1 = s[i][1] * scale;
            float tmax = fmaxf(sm0, sm1);
            #pragma unroll
            for (int off = 1; off < 16; off <<= 1)
                tmax = fmaxf(tmax, __shfl_xor_sync(0xffffffffu, tmax, off));
            float mnew = fmaxf(m_i[i], tmax);
            float alpha = __expf(m_i[i] - mnew);
            m_i[i] = mnew;
            float p0 = __expf(sm0 - mnew);
            float p1 = __expf(sm1 - mnew);
            Ps[ty * 4 + i][tx * 2 + 0] = p0;
            Ps[ty * 4 + i][tx * 2 + 1] = p1;
            float rs = p0 + p1;
            #pragma unroll
            for (int off = 1; off < 16; off <<= 1)
                rs += __shfl_xor_sync(0xffffffffu, rs, off);
            l_i[i] = l_i[i] * alpha + rs;
            #pragma unroll
            for (int j = 0; j < 4; ++j) o[i][j] *= alpha;
        }
        __syncthreads();

        // O += P (64x32) @ V (32x64)
        #pragma unroll 8
        for (int kk = 0; kk < 32; ++kk) {
            float p0 = Ps[ty * 4 + 0][kk];
            float p1 = Ps[ty * 4 + 1][kk];
            float p2 = Ps[ty * 4 + 2][kk];
            float p3 = Ps[ty * 4 + 3][kk];
            float v0 = Vs[kk][tx * 4 + 0];
            float v1 = Vs[kk][tx * 4 + 1];
            float v2 = Vs[kk][tx * 4 + 2];
            float v3 = Vs[kk][tx * 4 + 3];
            o[0][0] = fmaf(p0, v0, o[0][0]); o[0][1] = fmaf(p0, v1, o[0][1]);
            o[0][2] = fmaf(p0, v2, o[0][2]); o[0][3] = fmaf(p0, v3, o[0][3]);
            o[1][0] = fmaf(p1, v0, o[1][0]); o[1][1] = fmaf(p1, v1, o[1][1]);
            o[1][2] = fmaf(p1, v2, o[1][2]); o[1][3] = fmaf(p1, v3, o[1][3]);
            o[2][0] = fmaf(p2, v0, o[2][0]); o[2][1] = fmaf(p2, v1, o[2][1]);
            o[2][2] = fmaf(p2, v2, o[2][2]); o[2][3] = fmaf(p2, v3, o[2][3]);
            o[3][0] = fmaf(p3, v0, o[3][0]); o[3][1] = fmaf(p3, v1, o[3][1]);
            o[3][2] = fmaf(p3, v2, o[3][2]); o[3][3] = fmaf(p3, v3, o[3][3]);
        }
        __syncthreads();
    }

    // finalize: write ctx in [b, s, d] layout
    #pragma unroll
    for (int i = 0; i < 4; ++i) {
        float inv = 1.f / l_i[i];
        int tok = b * SEQ + qt * 64 + ty * 4 + i;
        float* cp = ctx + (size_t)tok * DMODEL + h * HDIM + tx * 4;
        #pragma unroll
        for (int j = 0; j < 4; ++j) cp[j] = o[i][j] * inv;
    }
}

// ---------------------------------------------------------------------------
// Residual + LayerNorm. One block per token row (1024 elems, 256 threads x f4).
// ---------------------------------------------------------------------------
__global__ void ln_kernel(const float* __restrict__ ctx,
                          const float* __restrict__ x,
                          const float* __restrict__ gamma,
                          const float* __restrict__ beta,
                          float* __restrict__ out)
{
    const int row = blockIdx.x;
    const int t   = threadIdx.x;
    const int lane = t & 31;
    const int warp = t >> 5;

    const float4 cv = ((const float4*)(ctx + (size_t)row * DMODEL))[t];
    const float4 xv = ((const float4*)(x   + (size_t)row * DMODEL))[t];
    float v0 = cv.x + xv.x, v1 = cv.y + xv.y, v2 = cv.z + xv.z, v3 = cv.w + xv.w;

    float sum = v0 + v1 + v2 + v3;
    float sq  = v0 * v0 + v1 * v1 + v2 * v2 + v3 * v3;

    #pragma unroll
    for (int off = 16; off > 0; off >>= 1) {
        sum += __shfl_xor_sync(0xffffffffu, sum, off);
        sq  += __shfl_xor_sync(0xffffffffu, sq,  off);
    }

    __shared__ float2 red[8];
    __shared__ float2 stats;
    if (lane == 0) red[warp] = make_float2(sum, sq);
    __syncthreads();
    if (warp == 0) {
        float2 p = (lane < 8) ? red[lane] : make_float2(0.f, 0.f);
        #pragma unroll
        for (int off = 4; off > 0; off >>= 1) {
            p.x += __shfl_xor_sync(0xffffffffu, p.x, off);
            p.y += __shfl_xor_sync(0xffffffffu, p.y, off);
        }
        if (lane == 0) {
            float mu  = p.x * (1.0f / DMODEL);
            float var = p.y * (1.0f / DMODEL) - mu * mu;
            stats = make_float2(mu, rsqrtf(var + 1e-5f));
        }
    }
    __syncthreads();

    const float mu = stats.x, rstd = stats.y;
    const float4 gv = ((const float4*)gamma)[t];
    const float4 bv = ((const float4*)beta)[t];
    float4 ov;
    ov.x = (v0 - mu) * rstd * gv.x + bv.x;
    ov.y = (v1 - mu) * rstd * gv.y + bv.y;
    ov.z = (v2 - mu) * rstd * gv.z + bv.z;
    ov.w = (v3 - mu) * rstd * gv.w + bv.w;
    ((float4*)(out + (size_t)row * DMODEL))[t] = ov;
}

// ---------------------------------------------------------------------------
extern "C" void kernel_launch(void* const* d_in, const int* in_sizes, int n_in,
                              void* d_out, int out_size)
{
    const float* x     = (const float*)d_in[0];
    const float* Wq    = (const float*)d_in[1];
    const float* bq    = (const float*)d_in[2];
    const float* Wk    = (const float*)d_in[3];
    const float* bk    = (const float*)d_in[4];
    const float* Wv    = (const float*)d_in[5];
    const float* bv    = (const float*)d_in[6];
    const float* gamma = (const float*)d_in[7];
    const float* beta  = (const float*)d_in[8];
    float* out = (float*)d_out;

    float *Qp, *Kp, *Vp, *Cp;
    cudaGetSymbolAddress((void**)&Qp, g_Q);
    cudaGetSymbolAddress((void**)&Kp, g_K);
    cudaGetSymbolAddress((void**)&Vp, g_V);
    cudaGetSymbolAddress((void**)&Cp, g_ctx);

    dim3 gemm_grid(DMODEL / 64, NTOK / 64);   // (16, 128)
    qkv_gemm_kernel<<<gemm_grid, 256>>>(x, Wq, bq, Qp);
    qkv_gemm_kernel<<<gemm_grid, 256>>>(x, Wk, bk, Kp);
    qkv_gemm_kernel<<<gemm_grid, 256>>>(x, Wv, bv, Vp);

    dim3 attn_grid(SEQ / 64, BATCH * NHEAD);  // (32, 64)
    attn_kernel<<<attn_grid, 256>>>(Qp, Kp, Vp, Cp);

    ln_kernel<<<NTOK, 256>>>(Cp, x, gamma, beta, out);
}

// round 3
// speedup vs baseline: 7.2792x; 7.2792x over previous
#include <cuda_runtime.h>
#include <cuda_fp16.h>
#include <cstdint>
#include <stdint.h>
#include <math.h>

#define BATCH 4
#define SEQ   2048
#define DMODEL 1024
#define NHEAD 16
#define HDIM  64
#define NTOK  (BATCH*SEQ)   // 8192
#define LDH   72            // smem row stride in halves (64 + 8 pad)

// ---------------- scratch (device globals; allocation forbidden) ----------
__device__ __half g_Xh[(size_t)NTOK * DMODEL];
__device__ __half g_Wh[3][(size_t)DMODEL * DMODEL];
__device__ __half g_Q [(size_t)NTOK * DMODEL];
__device__ __half g_K [(size_t)NTOK * DMODEL];
__device__ __half g_V [(size_t)NTOK * DMODEL];
__device__ float  g_ctx[(size_t)NTOK * DMODEL];

// ---------------- mma / ldmatrix helpers ----------------------------------
__device__ __forceinline__ uint32_t cvta_smem(const void* p) {
    return (uint32_t)__cvta_generic_to_shared(p);
}
__device__ __forceinline__ void ldm_x4(uint32_t* d, uint32_t a) {
    asm volatile("ldmatrix.sync.aligned.m8n8.x4.shared.b16 {%0,%1,%2,%3}, [%4];"
                 : "=r"(d[0]), "=r"(d[1]), "=r"(d[2]), "=r"(d[3]) : "r"(a));
}
__device__ __forceinline__ void ldm_x4_t(uint32_t* d, uint32_t a) {
    asm volatile("ldmatrix.sync.aligned.m8n8.x4.trans.shared.b16 {%0,%1,%2,%3}, [%4];"
                 : "=r"(d[0]), "=r"(d[1]), "=r"(d[2]), "=r"(d[3]) : "r"(a));
}
__device__ __forceinline__ void mma16816(float* c, const uint32_t* a, const uint32_t* b) {
    asm volatile("mma.sync.aligned.m16n8k16.row.col.f32.f16.f16.f32 "
                 "{%0,%1,%2,%3},{%4,%5,%6,%7},{%8,%9},{%0,%1,%2,%3};"
                 : "+f"(c[0]), "+f"(c[1]), "+f"(c[2]), "+f"(c[3])
                 : "r"(a[0]), "r"(a[1]), "r"(a[2]), "r"(a[3]), "r"(b[0]), "r"(b[1]));
}
__device__ __forceinline__ uint32_t packh2(float x, float y) {
    __half2 h = __floats2half2_rn(x, y);
    return *(uint32_t*)&h;
}

// ---------------- fp32 -> fp16 conversion ----------------------------------
__global__ void f2h_kernel(const float* __restrict__ in, __half* __restrict__ out, int n) {
    int i = (blockIdx.x * blockDim.x + threadIdx.x) * 4;
    if (i < n) {
        float4 v = *(const float4*)(in + i);
        __half2 a = __floats2half2_rn(v.x, v.y);
        __half2 b = __floats2half2_rn(v.z, v.w);
        ((__half2*)(out + i))[0] = a;
        ((__half2*)(out + i))[1] = b;
    }
}

// ---------------------------------------------------------------------------
// QKV projection: out[b,h,s,hd] = X[m,:] . W[n,:] + bias[n]   (fp16 HMMA)
// BM=128, BN=64 (one head), BK=64. 256 threads = 8 warps, warp = 16 m-rows.
// ---------------------------------------------------------------------------
__global__ __launch_bounds__(256) void proj_gemm(const __half* __restrict__ X,
                                                 const __half* __restrict__ W,
                                                 const float* __restrict__ bias,
                                                 __half* __restrict__ out)
{
    __shared__ __half As[128][LDH];
    __shared__ __half Bs[64][LDH];

    const int tid  = threadIdx.x;
    const int lane = tid & 31;
    const int warp = tid >> 5;
    const int bm = blockIdx.y * 128;
    const int bn = blockIdx.x * 64;     // one head per block-col

    float cf[8][4] = {};

    // A-frag ldmatrix base: rows warp*16+(lane&15), k-half (lane>>4)*8
    uint32_t a_base = cvta_smem(&As[warp * 16 + (lane & 15)][(lane >> 4) << 3]);
    // B-frag ldmatrix base: n rows ((lane>>4)<<3)+(lane&7), k-half ((lane>>3)&1)*8
    uint32_t b_base = cvta_smem(&Bs[((lane >> 4) << 3) + (lane & 7)][((lane >> 3) & 1) << 3]);

    for (int k0 = 0; k0 < DMODEL; k0 += 64) {
        #pragma unroll
        for (int i = 0; i < 4; ++i) {
            int f = tid + i * 256;          // 0..1023
            int r = f >> 3, c = (f & 7) * 8;
            *(uint4*)&As[r][c] = *(const uint4*)(X + (size_t)(bm + r) * DMODEL + k0 + c);
        }
        #pragma unroll
        for (int i = 0; i < 2; ++i) {
            int f = tid + i * 256;          // 0..511
            int r = f >> 3, c = (f & 7) * 8;
            *(uint4*)&Bs[r][c] = *(const uint4*)(W + (size_t)(bn + r) * DMODEL + k0 + c);
        }
        __syncthreads();

        uint32_t aa[4][4];
        #pragma unroll
        for (int ks = 0; ks < 4; ++ks) ldm_x4(aa[ks], a_base + ks * 32);

        #pragma unroll
        for (int ks = 0; ks < 4; ++ks) {
            #pragma unroll
            for (int np = 0; np < 4; ++np) {
                uint32_t bb[4];
                ldm_x4(bb, b_base + (np * 16 * LDH + ks * 16) * 2);
                mma16816(cf[2 * np],     aa[ks], bb);
                mma16816(cf[2 * np + 1], aa[ks], bb + 2);
            }
        }
        __syncthreads();
    }

    // epilogue: bias + fp16 store to [b,h,s,hd]
    const int h  = blockIdx.x;
    const int r0 = warp * 16 + (lane >> 2);
    const int cb = (lane & 3) * 2;
    const int tok0 = bm + r0;
    const int b0i = tok0 >> 11;                // /2048 (tile aligned: rows r0,r0+8 same b)
    const int s0  = tok0 & 2047;
    __half* o0 = out + (((size_t)b0i * NHEAD + h) * SEQ + s0) * HDIM;
    __half* o1 = o0 + 8 * HDIM;                // row r0+8
    #pragma unroll
    for (int j = 0; j < 8; ++j) {
        int n = bn + j * 8 + cb;
        float bz0 = bias[n], bz1 = bias[n + 1];
        *(__half2*)(o0 + j * 8 + cb) = __floats2half2_rn(cf[j][0] + bz0, cf[j][1] + bz1);
        *(__half2*)(o1 + j * 8 + cb) = __floats2half2_rn(cf[j][2] + bz0, cf[j][3] + bz1);
    }
}

// ---------------------------------------------------------------------------
// Flash attention (fp16 HMMA, fp32 accum). Block = (bh, 64-q tile), 4 warps.
// ---------------------------------------------------------------------------
__global__ __launch_bounds__(128) void attn_kernel(const __half* __restrict__ Q,
                                                   const __half* __restrict__ K,
                                                   const __half* __restrict__ V,
                                                   float* __restrict__ ctx)
{
    __shared__ __half Qs[64][LDH];
    __shared__ __half Ks[64][LDH];
    __shared__ __half Vs[64][LDH];

    const int tid  = threadIdx.x;
    const int lane = tid & 31;
    const int warp = tid >> 5;
    const int qt = blockIdx.x;
    const int bh = blockIdx.y;

    const __half* Qp = Q + ((size_t)bh * SEQ + qt * 64) * HDIM;
    #pragma unroll
    for (int i = 0; i < 4; ++i) {
        int f = tid + i * 128;              // 0..511
        int r = f >> 3, c = (f & 7) * 8;
        *(uint4*)&Qs[r][c] = *(const uint4*)(Qp + r * HDIM + c);
    }
    __syncthreads();

    uint32_t qa[4][4];
    {
        uint32_t qaddr = cvta_smem(&Qs[warp * 16 + (lane & 15)][(lane >> 4) << 3]);
        #pragma unroll
        for (int ks = 0; ks < 4; ++ks) ldm_x4(qa[ks], qaddr + ks * 32);
    }

    // K-frag base (non-trans), V-frag base (trans)
    uint32_t kaddr = cvta_smem(&Ks[((lane >> 4) << 3) + (lane & 7)][((lane >> 3) & 1) << 3]);
    uint32_t vaddr = cvta_smem(&Vs[(((lane >> 3) & 1) << 3) + (lane & 7)][(lane >> 4) << 3]);

    float of[8][4] = {};
    float m0 = -INFINITY, m1 = -INFINITY, l0 = 0.f, l1 = 0.f;
    const float scale = 0.125f;   // 1/sqrt(64)

    const __half* Kp = K + (size_t)bh * SEQ * HDIM;
    const __half* Vp = V + (size_t)bh * SEQ * HDIM;

    for (int kt = 0; kt < SEQ / 64; ++kt) {
        __syncthreads();
        #pragma unroll
        for (int i = 0; i < 4; ++i) {
            int f = tid + i * 128;
            int r = f >> 3, c = (f & 7) * 8;
            size_t g = (size_t)(kt * 64 + r) * HDIM + c;
            *(uint4*)&Ks[r][c] = *(const uint4*)(Kp + g);
            *(uint4*)&Vs[r][c] = *(const uint4*)(Vp + g);
        }
        __syncthreads();

        // S = Q . K^T  (m16 x n64 per warp)
        float sf[8][4] = {};
        #pragma unroll
        for (int ks = 0; ks < 4; ++ks) {
            #pragma unroll
            for (int np = 0; np < 4; ++np) {
                uint32_t bb[4];
                ldm_x4(bb, kaddr + (np * 16 * LDH + ks * 16) * 2);
                mma16816(sf[2 * np],     qa[ks], bb);
                mma16816(sf[2 * np + 1], qa[ks], bb + 2);
            }
        }

        // online softmax (rows r0 = lane>>2, r1 = r0+8)
        float rmax0 = -INFINITY, rmax1 = -INFINITY;
        #pragma unroll
        for (int j = 0; j < 8; ++j) {
            #pragma unroll
            for (int i = 0; i < 4; ++i) sf[j][i] *= scale;
            rmax0 = fmaxf(rmax0, fmaxf(sf[j][0], sf[j][1]));
            rmax1 = fmaxf(rmax1, fmaxf(sf[j][2], sf[j][3]));
        }
        rmax0 = fmaxf(rmax0, __shfl_xor_sync(0xffffffffu, rmax0, 1));
        rmax0 = fmaxf(rmax0, __shfl_xor_sync(0xffffffffu, rmax0, 2));
        rmax1 = fmaxf(rmax1, __shfl_xor_sync(0xffffffffu, rmax1, 1));
        rmax1 = fmaxf(rmax1, __shfl_xor_sync(0xffffffffu, rmax1, 2));

        float mn0 = fmaxf(m0, rmax0), mn1 = fmaxf(m1, rmax1);
        float alpha0 = __expf(m0 - mn0), alpha1 = __expf(m1 - mn1);
        m0 = mn0; m1 = mn1;

        float rs0 = 0.f, rs1 = 0.f;
        #pragma unroll
        for (int j = 0; j < 8; ++j) {
            sf[j][0] = __expf(sf[j][0] - mn0);
            sf[j][1] = __expf(sf[j][1] - mn0);
            sf[j][2] = __expf(sf[j][2] - mn1);
            sf[j][3] = __expf(sf[j][3] - mn1);
            rs0 += sf[j][0] + sf[j][1];
            rs1 += sf[j][2] + sf[j][3];
        }
        rs0 += __shfl_xor_sync(0xffffffffu, rs0, 1);
        rs0 += __shfl_xor_sync(0xffffffffu, rs0, 2);
        rs1 += __shfl_xor_sync(0xffffffffu, rs1, 1);
        rs1 += __shfl_xor_sync(0xffffffffu, rs1, 2);
        l0 = l0 * alpha0 + rs0;
        l1 = l1 * alpha1 + rs1;

        #pragma unroll
        for (int j = 0; j < 8; ++j) {
            of[j][0] *= alpha0; of[j][1] *= alpha0;
            of[j][2] *= alpha1; of[j][3] *= alpha1;
        }

        // O += P . V  (P fragments repacked from S accumulators)
        #pragma unroll
        for (int ks = 0; ks < 4; ++ks) {
            uint32_t pa[4];
            pa[0] = packh2(sf[2 * ks][0],     sf[2 * ks][1]);
            pa[1] = packh2(sf[2 * ks][2],     sf[2 * ks][3]);
            pa[2] = packh2(sf[2 * ks + 1][0], sf[2 * ks + 1][1]);
            pa[3] = packh2(sf[2 * ks + 1][2], sf[2 * ks + 1][3]);
            #pragma unroll
            for (int np = 0; np < 4; ++np) {
                uint32_t bb[4];
                ldm_x4_t(bb, vaddr + (ks * 16 * LDH + np * 16) * 2);
                mma16816(of[2 * np],     pa, bb);
                mma16816(of[2 * np + 1], pa, bb + 2);
            }
        }
    }

    // epilogue: ctx[b, s, d] fp32
    float inv0 = 1.f / l0, inv1 = 1.f / l1;
    int b = bh >> 4, h = bh & 15;
    int row0 = qt * 64 + warp * 16 + (lane >> 2);
    size_t tok0 = (size_t)b * SEQ + row0;
    int cb = (lane & 3) * 2;
    #pragma unroll
    for (int j = 0; j < 8; ++j) {
        float2 v0 = make_float2(of[j][0] * inv0, of[j][1] * inv0);
        float2 v1 = make_float2(of[j][2] * inv1, of[j][3] * inv1);
        *(float2*)(ctx + tok0 * DMODEL + h * HDIM + j * 8 + cb) = v0;
        *(float2*)(ctx + (tok0 + 8) * DMODEL + h * HDIM + j * 8 + cb) = v1;
    }
}

// ---------------------------------------------------------------------------
// Residual + LayerNorm. One block per token row.
// ---------------------------------------------------------------------------
__global__ void ln_kernel(const float* __restrict__ ctx,
                          const float* __restrict__ x,
                          const float* __restrict__ gamma,
                          const float* __restrict__ beta,
                          float* __restrict__ out)
{
    const int row = blockIdx.x;
    const int t = threadIdx.x;
    const int lane = t & 31;
    const int warp = t >> 5;

    const float4 cv = ((const float4*)(ctx + (size_t)row * DMODEL))[t];
    const float4 xv = ((const float4*)(x   + (size_t)row * DMODEL))[t];
    float v0 = cv.x + xv.x, v1 = cv.y + xv.y, v2 = cv.z + xv.z, v3 = cv.w + xv.w;

    float sum = v0 + v1 + v2 + v3;
    float sq  = v0 * v0 + v1 * v1 + v2 * v2 + v3 * v3;
    #pragma unroll
    for (int off = 16; off > 0; off >>= 1) {
        sum += __shfl_xor_sync(0xffffffffu, sum, off);
        sq  += __shfl_xor_sync(0xffffffffu, sq,  off);
    }

    __shared__ float2 red[8];
    __shared__ float2 stats;
    if (lane == 0) red[warp] = make_float2(sum, sq);
    __syncthreads();
    if (warp == 0) {
        float2 p = (lane < 8) ? red[lane] : make_float2(0.f, 0.f);
        #pragma unroll
        for (int off = 4; off > 0; off >>= 1) {
            p.x += __shfl_xor_sync(0xffffffffu, p.x, off);
            p.y += __shfl_xor_sync(0xffffffffu, p.y, off);
        }
        if (lane == 0) {
            float mu  = p.x * (1.0f / DMODEL);
            float var = p.y * (1.0f / DMODEL) - mu * mu;
            stats = make_float2(mu, rsqrtf(var + 1e-5f));
        }
    }
    __syncthreads();

    const float mu = stats.x, rstd = stats.y;
    const float4 gv = ((const float4*)gamma)[t];
    const float4 bv = ((const float4*)beta)[t];
    float4 ov;
    ov.x = (v0 - mu) * rstd * gv.x + bv.x;
    ov.y = (v1 - mu) * rstd * gv.y + bv.y;
    ov.z = (v2 - mu) * rstd * gv.z + bv.z;
    ov.w = (v3 - mu) * rstd * gv.w + bv.w;
    ((float4*)(out + (size_t)row * DMODEL))[t] = ov;
}

// ---------------------------------------------------------------------------
extern "C" void kernel_launch(void* const* d_in, const int* in_sizes, int n_in,
                              void* d_out, int out_size)
{
    const float* x     = (const float*)d_in[0];
    const float* Wq    = (const float*)d_in[1];
    const float* bq    = (const float*)d_in[2];
    const float* Wk    = (const float*)d_in[3];
    const float* bk    = (const float*)d_in[4];
    const float* Wv    = (const float*)d_in[5];
    const float* bv    = (const float*)d_in[6];
    const float* gamma = (const float*)d_in[7];
    const float* beta  = (const float*)d_in[8];
    float* out = (float*)d_out;

    __half *Xh, *Wh, *Qp, *Kp, *Vp;
    float* Cp;
    cudaGetSymbolAddress((void**)&Xh, g_Xh);
    cudaGetSymbolAddress((void**)&Wh, g_Wh);
    cudaGetSymbolAddress((void**)&Qp, g_Q);
    cudaGetSymbolAddress((void**)&Kp, g_K);
    cudaGetSymbolAddress((void**)&Vp, g_V);
    cudaGetSymbolAddress((void**)&Cp, g_ctx);

    const int NX = NTOK * DMODEL;          // 8388608
    const int NW = DMODEL * DMODEL;        // 1048576
    f2h_kernel<<<NX / 4 / 256, 256>>>(x,  Xh, NX);
    f2h_kernel<<<NW / 4 / 256, 256>>>(Wq, Wh + 0 * (size_t)NW, NW);
    f2h_kernel<<<NW / 4 / 256, 256>>>(Wk, Wh + 1 * (size_t)NW, NW);
    f2h_kernel<<<NW / 4 / 256, 256>>>(Wv, Wh + 2 * (size_t)NW, NW);

    dim3 gemm_grid(DMODEL / 64, NTOK / 128);   // (16, 64)
    proj_gemm<<<gemm_grid, 256>>>(Xh, Wh + 0 * (size_t)NW, bq, Qp);
    proj_gemm<<<gemm_grid, 256>>>(Xh, Wh + 1 * (size_t)NW, bk, Kp);
    proj_gemm<<<gemm_grid, 256>>>(Xh, Wh + 2 * (size_t)NW, bv, Vp);

    dim3 attn_grid(SEQ / 64, BATCH * NHEAD);   // (32, 64)
    attn_kernel<<<attn_grid, 128>>>(Qp, Kp, Vp, Cp);

    ln_kernel<<<NTOK, 256>>>(Cp, x, gamma, beta, out);
}

// round 4
// speedup vs baseline: 8.9157x; 1.2248x over previous
#include <cuda_runtime.h>
#include <cuda_fp16.h>
#include <cstdint>
#include <stdint.h>
#include <math.h>

#define BATCH 4
#define SEQ   2048
#define DMODEL 1024
#define NHEAD 16
#define HDIM  64
#define NTOK  (BATCH*SEQ)   // 8192
#define LDH   72            // smem row stride in halves (64 + 8 pad; 144B = 9*16 -> 16B aligned rows)

// ---------------- scratch (device globals; allocation forbidden) ----------
__device__ __half g_Xh[(size_t)NTOK * DMODEL];
__device__ __half g_Wh[3][(size_t)DMODEL * DMODEL];
__device__ __half g_Q [(size_t)NTOK * DMODEL];
__device__ __half g_K [(size_t)NTOK * DMODEL];
__device__ __half g_V [(size_t)NTOK * DMODEL];
__device__ float  g_ctx[(size_t)NTOK * DMODEL];

// ---------------- helpers ---------------------------------------------------
__device__ __forceinline__ uint32_t cvta_smem(const void* p) {
    return (uint32_t)__cvta_generic_to_shared(p);
}
__device__ __forceinline__ void ldm_x4(uint32_t* d, uint32_t a) {
    asm volatile("ldmatrix.sync.aligned.m8n8.x4.shared.b16 {%0,%1,%2,%3}, [%4];"
                 : "=r"(d[0]), "=r"(d[1]), "=r"(d[2]), "=r"(d[3]) : "r"(a));
}
__device__ __forceinline__ void ldm_x4_t(uint32_t* d, uint32_t a) {
    asm volatile("ldmatrix.sync.aligned.m8n8.x4.trans.shared.b16 {%0,%1,%2,%3}, [%4];"
                 : "=r"(d[0]), "=r"(d[1]), "=r"(d[2]), "=r"(d[3]) : "r"(a));
}
__device__ __forceinline__ void mma16816(float* c, const uint32_t* a, const uint32_t* b) {
    asm volatile("mma.sync.aligned.m16n8k16.row.col.f32.f16.f16.f32 "
                 "{%0,%1,%2,%3},{%4,%5,%6,%7},{%8,%9},{%0,%1,%2,%3};"
                 : "+f"(c[0]), "+f"(c[1]), "+f"(c[2]), "+f"(c[3])
                 : "r"(a[0]), "r"(a[1]), "r"(a[2]), "r"(a[3]), "r"(b[0]), "r"(b[1]));
}
__device__ __forceinline__ uint32_t packh2(float x, float y) {
    __half2 h = __floats2half2_rn(x, y);
    return *(uint32_t*)&h;
}
__device__ __forceinline__ void cp16(uint32_t dst, const void* src) {
    asm volatile("cp.async.cg.shared.global [%0], [%1], 16;" :: "r"(dst), "l"(src));
}
__device__ __forceinline__ void cp_commit() {
    asm volatile("cp.async.commit_group;");
}
__device__ __forceinline__ void cp_wait0() {
    asm volatile("cp.async.wait_group 0;");
}

// ---------------- fp32 -> fp16 conversion ----------------------------------
__global__ void f2h_kernel(const float* __restrict__ in, __half* __restrict__ out, int n) {
    int i = (blockIdx.x * blockDim.x + threadIdx.x) * 4;
    if (i < n) {
        float4 v = *(const float4*)(in + i);
        ((__half2*)(out + i))[0] = __floats2half2_rn(v.x, v.y);
        ((__half2*)(out + i))[1] = __floats2half2_rn(v.z, v.w);
    }
}

// ---------------------------------------------------------------------------
// QKV projection (fused, z = 0/1/2 -> Q/K/V). fp16 HMMA, cp.async 2-stage.
// BM=128, BN=64 (one head), BK=64. 256 threads = 8 warps, warp = 16 m-rows.
// dyn smem: stage s at sm + s*(192*LDH): A = 128 rows, B = 64 rows.
// ---------------------------------------------------------------------------
#define PROJ_STG (192 * LDH)
#define PROJ_SMEM (2 * PROJ_STG * 2)   // bytes = 55296

__global__ __launch_bounds__(256) void proj_gemm(const __half* __restrict__ X,
                                                 const __half* __restrict__ W0,
                                                 const __half* __restrict__ W1,
                                                 const __half* __restrict__ W2,
                                                 const float* __restrict__ b0,
                                                 const float* __restrict__ b1,
                                                 const float* __restrict__ b2,
                                                 __half* __restrict__ o0,
                                                 __half* __restrict__ o1,
                                                 __half* __restrict__ o2)
{
    extern __shared__ __half sm[];
    const __half* W = (blockIdx.z == 0) ? W0 : (blockIdx.z == 1) ? W1 : W2;
    const float* bias = (blockIdx.z == 0) ? b0 : (blockIdx.z == 1) ? b1 : b2;
    __half* out = (blockIdx.z == 0) ? o0 : (blockIdx.z == 1) ? o1 : o2;

    const int tid  = threadIdx.x;
    const int lane = tid & 31;
    const int warp = tid >> 5;
    const int bm = blockIdx.y * 128;
    const int bn = blockIdx.x * 64;

    __half* As[2] = { sm,            sm + PROJ_STG };
    __half* Bs[2] = { sm + 128*LDH,  sm + PROJ_STG + 128*LDH };

    // cp.async load of one stage (A: 1024 chunks, B: 512 chunks; 16B each)
    auto load_stage = [&](int s, int k0) {
        #pragma unroll
        for (int i = 0; i < 4; ++i) {
            int f = tid + i * 256;
            int r = f >> 3, c = (f & 7) * 8;
            cp16(cvta_smem(As[s] + r * LDH + c),
                 X + (size_t)(bm + r) * DMODEL + k0 + c);
        }
        #pragma unroll
        for (int i = 0; i < 2; ++i) {
            int f = tid + i * 256;
            int r = f >> 3, c = (f & 7) * 8;
            cp16(cvta_smem(Bs[s] + r * LDH + c),
                 W + (size_t)(bn + r) * DMODEL + k0 + c);
        }
        cp_commit();
    };

    // per-stage ldmatrix bases
    uint32_t a_base[2], b_base[2];
    #pragma unroll
    for (int s = 0; s < 2; ++s) {
        a_base[s] = cvta_smem(As[s] + (warp * 16 + (lane & 15)) * LDH + ((lane >> 4) << 3));
        b_base[s] = cvta_smem(Bs[s] + (((lane >> 4) << 3) + (lane & 7)) * LDH + (((lane >> 3) & 1) << 3));
    }

    float cf[8][4] = {};

    load_stage(0, 0);
    #pragma unroll 1
    for (int ki = 0; ki < DMODEL / 64; ++ki) {
        cp_wait0();
        __syncthreads();
        if (ki + 1 < DMODEL / 64) load_stage((ki + 1) & 1, (ki + 1) * 64);

        const int s = ki & 1;
        uint32_t aa[4][4];
        #pragma unroll
        for (int ks = 0; ks < 4; ++ks) ldm_x4(aa[ks], a_base[s] + ks * 32);

        #pragma unroll
        for (int ks = 0; ks < 4; ++ks) {
            #pragma unroll
            for (int np = 0; np < 4; ++np) {
                uint32_t bb[4];
                ldm_x4(bb, b_base[s] + (np * 16 * LDH + ks * 16) * 2);
                mma16816(cf[2 * np],     aa[ks], bb);
                mma16816(cf[2 * np + 1], aa[ks], bb + 2);
            }
        }
        __syncthreads();
    }

    // epilogue: bias + fp16 store to [b,h,s,hd]
    const int h  = blockIdx.x;
    const int r0 = warp * 16 + (lane >> 2);
    const int cb = (lane & 3) * 2;
    const int tok0 = bm + r0;
    const int b0i = tok0 >> 11;
    const int s0  = tok0 & 2047;
    __half* p0 = out + (((size_t)b0i * NHEAD + h) * SEQ + s0) * HDIM;
    __half* p1 = p0 + 8 * HDIM;
    #pragma unroll
    for (int j = 0; j < 8; ++j) {
        int n = bn + j * 8 + cb;
        float bz0 = bias[n], bz1 = bias[n + 1];
        *(__half2*)(p0 + j * 8 + cb) = __floats2half2_rn(cf[j][0] + bz0, cf[j][1] + bz1);
        *(__half2*)(p1 + j * 8 + cb) = __floats2half2_rn(cf[j][2] + bz0, cf[j][3] + bz1);
    }
}

// ---------------------------------------------------------------------------
// Flash attention (fp16 HMMA, fp32 accum, cp.async 2-stage K/V).
// Block = (bh, 128-q tile), 8 warps (256 thr). K/V tile = 64 rows.
// dyn smem: Q[128*LDH] | stage0 {K 64, V 64} | stage1 {K 64, V 64}
// ---------------------------------------------------------------------------
#define ATTN_QSZ  (128 * LDH)
#define ATTN_KVST (128 * LDH)                       // K(64)+V(64) rows per stage
#define ATTN_SMEM ((ATTN_QSZ + 2 * ATTN_KVST) * 2)  // bytes = 55296

__global__ __launch_bounds__(256) void attn_kernel(const __half* __restrict__ Q,
                                                   const __half* __restrict__ K,
                                                   const __half* __restrict__ V,
                                                   float* __restrict__ ctx)
{
    extern __shared__ __half sm[];
    __half* Qs = sm;
    __half* Ks[2] = { sm + ATTN_QSZ,            sm + ATTN_QSZ + ATTN_KVST };
    __half* Vs[2] = { sm + ATTN_QSZ + 64 * LDH, sm + ATTN_QSZ + ATTN_KVST + 64 * LDH };

    const int tid  = threadIdx.x;
    const int lane = tid & 31;
    const int warp = tid >> 5;
    const int qt = blockIdx.x;         // 0..15 (128-row q tiles)
    const int bh = blockIdx.y;

    const __half* Kp = K + (size_t)bh * SEQ * HDIM;
    const __half* Vp = V + (size_t)bh * SEQ * HDIM;

    auto load_kv = [&](int s, int kt) {
        const __half* ksrc = Kp + (size_t)kt * 64 * HDIM;
        const __half* vsrc = Vp + (size_t)kt * 64 * HDIM;
        #pragma unroll
        for (int i = 0; i < 2; ++i) {
            int f = tid + i * 256;          // 0..511
            int r = f >> 3, c = (f & 7) * 8;
            cp16(cvta_smem(Ks[s] + r * LDH + c), ksrc + (size_t)r * HDIM + c);
            cp16(cvta_smem(Vs[s] + r * LDH + c), vsrc + (size_t)r * HDIM + c);
        }
        cp_commit();
    };

    // prefetch stage 0 K/V, then fill Q (regular stores)
    load_kv(0, 0);
    const __half* Qp = Q + ((size_t)bh * SEQ + qt * 128) * HDIM;
    #pragma unroll
    for (int i = 0; i < 4; ++i) {
        int f = tid + i * 256;              // 0..1023
        int r = f >> 3, c = (f & 7) * 8;
        *(uint4*)&Qs[r * LDH + c] = *(const uint4*)(Qp + (size_t)r * HDIM + c);
    }
    __syncthreads();

    uint32_t qa[4][4];
    {
        uint32_t qaddr = cvta_smem(Qs + (warp * 16 + (lane & 15)) * LDH + ((lane >> 4) << 3));
        #pragma unroll
        for (int ks = 0; ks < 4; ++ks) ldm_x4(qa[ks], qaddr + ks * 32);
    }

    uint32_t kaddr[2], vaddr[2];
    #pragma unroll
    for (int s = 0; s < 2; ++s) {
        kaddr[s] = cvta_smem(Ks[s] + (((lane >> 4) << 3) + (lane & 7)) * LDH + (((lane >> 3) & 1) << 3));
        vaddr[s] = cvta_smem(Vs[s] + ((((lane >> 3) & 1) << 3) + (lane & 7)) * LDH + ((lane >> 4) << 3));
    }

    float of[8][4] = {};
    float m0 = -INFINITY, m1 = -INFINITY, l0 = 0.f, l1 = 0.f;
    const float scale = 0.125f;   // 1/sqrt(64)

    #pragma unroll 1
    for (int kt = 0; kt < SEQ / 64; ++kt) {
        cp_wait0();
        __syncthreads();
        if (kt + 1 < SEQ / 64) load_kv((kt + 1) & 1, kt + 1);
        const int s = kt & 1;

        // S = Q . K^T  (m16 x n64 per warp)
        float sf[8][4] = {};
        #pragma unroll
        for (int ks = 0; ks < 4; ++ks) {
            #pragma unroll
            for (int np = 0; np < 4; ++np) {
                uint32_t bb[4];
                ldm_x4(bb, kaddr[s] + (np * 16 * LDH + ks * 16) * 2);
                mma16816(sf[2 * np],     qa[ks], bb);
                mma16816(sf[2 * np + 1], qa[ks], bb + 2);
            }
        }

        // online softmax (rows r0 = lane>>2, r1 = r0+8)
        float rmax0 = -INFINITY, rmax1 = -INFINITY;
        #pragma unroll
        for (int j = 0; j < 8; ++j) {
            #pragma unroll
            for (int i = 0; i < 4; ++i) sf[j][i] *= scale;
            rmax0 = fmaxf(rmax0, fmaxf(sf[j][0], sf[j][1]));
            rmax1 = fmaxf(rmax1, fmaxf(sf[j][2], sf[j][3]));
        }
        rmax0 = fmaxf(rmax0, __shfl_xor_sync(0xffffffffu, rmax0, 1));
        rmax0 = fmaxf(rmax0, __shfl_xor_sync(0xffffffffu, rmax0, 2));
        rmax1 = fmaxf(rmax1, __shfl_xor_sync(0xffffffffu, rmax1, 1));
        rmax1 = fmaxf(rmax1, __shfl_xor_sync(0xffffffffu, rmax1, 2));

        float mn0 = fmaxf(m0, rmax0), mn1 = fmaxf(m1, rmax1);
        float alpha0 = __expf(m0 - mn0), alpha1 = __expf(m1 - mn1);
        m0 = mn0; m1 = mn1;

        float rs0 = 0.f, rs1 = 0.f;
        #pragma unroll
        for (int j = 0; j < 8; ++j) {
            sf[j][0] = __expf(sf[j][0] - mn0);
            sf[j][1] = __expf(sf[j][1] - mn0);
            sf[j][2] = __expf(sf[j][2] - mn1);
            sf[j][3] = __expf(sf[j][3] - mn1);
            rs0 += sf[j][0] + sf[j][1];
            rs1 += sf[j][2] + sf[j][3];
        }
        rs0 += __shfl_xor_sync(0xffffffffu, rs0, 1);
        rs0 += __shfl_xor_sync(0xffffffffu, rs0, 2);
        rs1 += __shfl_xor_sync(0xffffffffu, rs1, 1);
        rs1 += __shfl_xor_sync(0xffffffffu, rs1, 2);
        l0 = l0 * alpha0 + rs0;
        l1 = l1 * alpha1 + rs1;

        #pragma unroll
        for (int j = 0; j < 8; ++j) {
            of[j][0] *= alpha0; of[j][1] *= alpha0;
            of[j][2] *= alpha1; of[j][3] *= alpha1;
        }

        // O += P . V
        #pragma unroll
        for (int ks = 0; ks < 4; ++ks) {
            uint32_t pa[4];
            pa[0] = packh2(sf[2 * ks][0],     sf[2 * ks][1]);
            pa[1] = packh2(sf[2 * ks][2],     sf[2 * ks][3]);
            pa[2] = packh2(sf[2 * ks + 1][0], sf[2 * ks + 1][1]);
            pa[3] = packh2(sf[2 * ks + 1][2], sf[2 * ks + 1][3]);
            #pragma unroll
            for (int np = 0; np < 4; ++np) {
                uint32_t bb[4];
                ldm_x4_t(bb, vaddr[s] + (ks * 16 * LDH + np * 16) * 2);
                mma16816(of[2 * np],     pa, bb);
                mma16816(of[2 * np + 1], pa, bb + 2);
            }
        }
        __syncthreads();
    }

    // epilogue: ctx[b, s, d] fp32
    float inv0 = 1.f / l0, inv1 = 1.f / l1;
    int b = bh >> 4, h = bh & 15;
    int row0 = qt * 128 + warp * 16 + (lane >> 2);
    size_t tok0 = (size_t)b * SEQ + row0;
    int cb = (lane & 3) * 2;
    #pragma unroll
    for (int j = 0; j < 8; ++j) {
        float2 v0 = make_float2(of[j][0] * inv0, of[j][1] * inv0);
        float2 v1 = make_float2(of[j][2] * inv1, of[j][3] * inv1);
        *(float2*)(ctx + tok0 * DMODEL + h * HDIM + j * 8 + cb) = v0;
        *(float2*)(ctx + (tok0 + 8) * DMODEL + h * HDIM + j * 8 + cb) = v1;
    }
}

// ---------------------------------------------------------------------------
// Residual + LayerNorm. One block per token row.
// ---------------------------------------------------------------------------
__global__ void ln_kernel(const float* __restrict__ ctx,
                          const float* __restrict__ x,
                          const float* __restrict__ gamma,
                          const float* __restrict__ beta,
                          float* __restrict__ out)
{
    const int row = blockIdx.x;
    const int t = threadIdx.x;
    const int lane = t & 31;
    const int warp = t >> 5;

    const float4 cv = ((const float4*)(ctx + (size_t)row * DMODEL))[t];
    const float4 xv = ((const float4*)(x   + (size_t)row * DMODEL))[t];
    float v0 = cv.x + xv.x, v1 = cv.y + xv.y, v2 = cv.z + xv.z, v3 = cv.w + xv.w;

    float sum = v0 + v1 + v2 + v3;
    float sq  = v0 * v0 + v1 * v1 + v2 * v2 + v3 * v3;
    #pragma unroll
    for (int off = 16; off > 0; off >>= 1) {
        sum += __shfl_xor_sync(0xffffffffu, sum, off);
        sq  += __shfl_xor_sync(0xffffffffu, sq,  off);
    }

    __shared__ float2 red[8];
    __shared__ float2 stats;
    if (lane == 0) red[warp] = make_float2(sum, sq);
    __syncthreads();
    if (warp == 0) {
        float2 p = (lane < 8) ? red[lane] : make_float2(0.f, 0.f);
        #pragma unroll
        for (int off = 4; off > 0; off >>= 1) {
            p.x += __shfl_xor_sync(0xffffffffu, p.x, off);
            p.y += __shfl_xor_sync(0xffffffffu, p.y, off);
        }
        if (lane == 0) {
            float mu  = p.x * (1.0f / DMODEL);
            float var = p.y * (1.0f / DMODEL) - mu * mu;
            stats = make_float2(mu, rsqrtf(var + 1e-5f));
        }
    }
    __syncthreads();

    const float mu = stats.x, rstd = stats.y;
    const float4 gv = ((const float4*)gamma)[t];
    const float4 bv = ((const float4*)beta)[t];
    float4 ov;
    ov.x = (v0 - mu) * rstd * gv.x + bv.x;
    ov.y = (v1 - mu) * rstd * gv.y + bv.y;
    ov.z = (v2 - mu) * rstd * gv.z + bv.z;
    ov.w = (v3 - mu) * rstd * gv.w + bv.w;
    ((float4*)(out + (size_t)row * DMODEL))[t] = ov;
}

// ---------------------------------------------------------------------------
extern "C" void kernel_launch(void* const* d_in, const int* in_sizes, int n_in,
                              void* d_out, int out_size)
{
    const float* x     = (const float*)d_in[0];
    const float* Wq    = (const float*)d_in[1];
    const float* bq    = (const float*)d_in[2];
    const float* Wk    = (const float*)d_in[3];
    const float* bk    = (const float*)d_in[4];
    const float* Wv    = (const float*)d_in[5];
    const float* bv    = (const float*)d_in[6];
    const float* gamma = (const float*)d_in[7];
    const float* beta  = (const float*)d_in[8];
    float* out = (float*)d_out;

    __half *Xh, *Wh, *Qp, *Kp, *Vp;
    float* Cp;
    cudaGetSymbolAddress((void**)&Xh, g_Xh);
    cudaGetSymbolAddress((void**)&Wh, g_Wh);
    cudaGetSymbolAddress((void**)&Qp, g_Q);
    cudaGetSymbolAddress((void**)&Kp, g_K);
    cudaGetSymbolAddress((void**)&Vp, g_V);
    cudaGetSymbolAddress((void**)&Cp, g_ctx);

    static bool attr_done = false;
    if (!attr_done) {
        cudaFuncSetAttribute(proj_gemm, cudaFuncAttributeMaxDynamicSharedMemorySize, PROJ_SMEM);
        cudaFuncSetAttribute(attn_kernel, cudaFuncAttributeMaxDynamicSharedMemorySize, ATTN_SMEM);
        attr_done = true;
    }

    const int NX = NTOK * DMODEL;          // 8388608
    const int NW = DMODEL * DMODEL;        // 1048576
    f2h_kernel<<<NX / 4 / 256, 256>>>(x,  Xh, NX);
    f2h_kernel<<<NW / 4 / 256, 256>>>(Wq, Wh + 0 * (size_t)NW, NW);
    f2h_kernel<<<NW / 4 / 256, 256>>>(Wk, Wh + 1 * (size_t)NW, NW);
    f2h_kernel<<<NW / 4 / 256, 256>>>(Wv, Wh + 2 * (size_t)NW, NW);

    dim3 gemm_grid(DMODEL / 64, NTOK / 128, 3);   // (16, 64, 3)
    proj_gemm<<<gemm_grid, 256, PROJ_SMEM>>>(Xh,
        Wh + 0 * (size_t)NW, Wh + 1 * (size_t)NW, Wh + 2 * (size_t)NW,
        bq, bk, bv, Qp, Kp, Vp);

    dim3 attn_grid(SEQ / 128, BATCH * NHEAD);     // (16, 64)
    attn_kernel<<<attn_grid, 256, ATTN_SMEM>>>(Qp, Kp, Vp, Cp);

    ln_kernel<<<NTOK, 256>>>(Cp, x, gamma, beta, out);
}